// round 4
// baseline (speedup 1.0000x reference)
#include <cuda_runtime.h>
#include <cstdint>

#define VV 49688
#define DD 128
#define BB 16
#define NN 100

// Per-(node,batch) tag: 0 = not updated, else x-row-index+1.
// Statically zero-initialized; the fused kernel clears entries it consumes,
// so the all-zero invariant holds across graph replays.
__device__ unsigned short g_tag[VV * BB];   // 1.59 MB

__global__ void __launch_bounds__(256) scatter_tags_kernel(
    const int* __restrict__ nodes)
{
    int g = blockIdx.x * blockDim.x + threadIdx.x;
    if (g >= BB * NN) return;
    int b = g / NN;
    int i = g - b * NN;
    int node = __ldg(&nodes[g]);
    g_tag[(size_t)node * BB + b] = (unsigned short)(i + 1);
}

// One thread per float4 of W (1.59M threads). Each warp owns exactly one W row
// (32 float4 = 128 floats). Fast path (tags all zero, ~96.8% of warps): pure
// 16-way broadcast store. Slow path: blend tagged batches with x, then lane 0
// clears the tags.
__global__ void __launch_bounds__(256) fused_copy_blend_kernel(
    const float4* __restrict__ W4,
    const float*  __restrict__ x,
    const float*  __restrict__ alpha,
    float4* __restrict__ out4)
{
    const int nvec = VV * (DD / 4);               // 1,590,016 float4 per copy
    int j = blockIdx.x * blockDim.x + threadIdx.x;
    if (j >= nvec) return;
    int v = j >> 5;                               // W row
    int t = j & 31;                               // float4 lane within row

    float4 w = __ldg(&W4[j]);

    const uint4* tp = (const uint4*)&g_tag[(size_t)v * BB];
    uint4 t0 = __ldg(&tp[0]);                     // tags b=0..7  (lane-invariant)
    uint4 t1 = __ldg(&tp[1]);                     // tags b=8..15
    unsigned any = t0.x | t0.y | t0.z | t0.w | t1.x | t1.y | t1.z | t1.w;

    size_t base = (size_t)j;
    if (any == 0) {
#pragma unroll
        for (int b = 0; b < BB; ++b) {
            __stcs(&out4[base], w);
            base += (size_t)nvec;
        }
    } else {
        float a = __ldg(&alpha[v]);
        float oma = 1.0f - a;
        unsigned words[8] = {t0.x, t0.y, t0.z, t0.w, t1.x, t1.y, t1.z, t1.w};
#pragma unroll
        for (int b = 0; b < BB; ++b) {
            unsigned tg = (words[b >> 1] >> ((b & 1) * 16)) & 0xFFFFu;
            float4 r = w;
            if (tg) {
                const float4* xr = (const float4*)(x + (size_t)(tg - 1) * DD);
                float4 xv = __ldg(&xr[t]);
                r.x = oma * w.x + a * xv.x;
                r.y = oma * w.y + a * xv.y;
                r.z = oma * w.z + a * xv.z;
                r.w = oma * w.w + a * xv.w;
            }
            __stcs(&out4[base], r);
            base += (size_t)nvec;
        }
        __syncwarp();
        if (t == 0) {                             // restore all-zero invariant
            uint4 z = make_uint4(0u, 0u, 0u, 0u);
            uint4* tw = (uint4*)&g_tag[(size_t)v * BB];
            tw[0] = z;
            tw[1] = z;
        }
    }
}

extern "C" void kernel_launch(void* const* d_in, const int* in_sizes, int n_in,
                              void* d_out, int out_size)
{
    const int*   nodes = (const int*)d_in[0];
    const float* x     = (const float*)d_in[1];
    const float* W     = (const float*)d_in[2];
    const float* alpha = (const float*)d_in[3];
    float*       out   = (float*)d_out;

    scatter_tags_kernel<<<(BB * NN + 255) / 256, 256>>>(nodes);

    const int nvec = VV * (DD / 4);
    fused_copy_blend_kernel<<<(nvec + 255) / 256, 256>>>(
        (const float4*)W, x, alpha, (float4*)out);
}